// round 1
// baseline (speedup 1.0000x reference)
#include <cuda_runtime.h>
#include <cuda_bf16.h>
#include <cstdint>

#define B_SZ 1024
#define E_SZ 512
#define C_SZ 16384

#define BM 128
#define BN 64
#define BK 32
#define SA 40   // padded smem stride (bf16 units): 20 words, stride%32==20 -> conflict-free frag loads

// ---------------- scratch (static device memory; no runtime alloc) ----------------
__device__ __nv_bfloat16 g_proxyB[C_SZ * E_SZ];   // normalized proxies, bf16
__device__ __nv_bfloat16 g_inputB[B_SZ * E_SZ];   // inputs, bf16
__device__ float g_outlier[C_SZ];
__device__ float g_invEff[C_SZ];
__device__ int   g_cnt[C_SZ];
__device__ float g_Spos[C_SZ];
__device__ float g_Sneg[C_SZ];
__device__ float g_Nsum[C_SZ];

// ---------------- fast exp on FMA pipe (avoids MUFU bottleneck) ----------------
__device__ __forceinline__ float fexp(float x) {
    float t = x * 1.44269504088896341f;
    float fi = rintf(t);
    float f = t - fi;
    // 2^f, |f|<=0.5, Taylor deg-6 in ln2 powers; rel err ~1e-7
    float p = 1.54035303933816e-4f;
    p = fmaf(p, f, 1.33335581467049e-3f);
    p = fmaf(p, f, 9.61812910762848e-3f);
    p = fmaf(p, f, 5.55041086648216e-2f);
    p = fmaf(p, f, 2.40226506959101e-1f);
    p = fmaf(p, f, 6.93147180559945e-1f);
    p = fmaf(p, f, 1.0f);
    int i = (int)fi;
    float s = __int_as_float((i + 127) << 23);
    return p * s;
}

// ---------------- prep kernels ----------------
__global__ void initKernel(const float* __restrict__ effN, const float* __restrict__ ls) {
    int c = blockIdx.x * blockDim.x + threadIdx.x;
    if (c >= C_SZ) return;
    float eff = effN[c], l = ls[c];
    float wb = 1.0f / (1.0f + log1pf(eff));
    float eta = (1.0f + (1.0f - l)) * wb + 0.1f;   // K=1, LAM=0.1
    g_outlier[c] = l - eta;
    g_invEff[c] = 1.0f / fmaxf(1.0f, eff);
    g_cnt[c] = 0;
    g_Spos[c] = 0.0f;
    g_Sneg[c] = 0.0f;
    g_Nsum[c] = 0.0f;
}

__global__ void cntKernel(const int* __restrict__ t) {
    int i = blockIdx.x * blockDim.x + threadIdx.x;
    if (i < B_SZ) atomicAdd(&g_cnt[t[i]], 1);
}

__global__ void convInputKernel(const float* __restrict__ in) {
    int i = blockIdx.x * blockDim.x + threadIdx.x;   // over B*E/4 float4s
    float4 v = ((const float4*)in)[i];
    __nv_bfloat162* o = (__nv_bfloat162*)g_inputB;
    o[i * 2]     = __floats2bfloat162_rn(v.x, v.y);
    o[i * 2 + 1] = __floats2bfloat162_rn(v.z, v.w);
}

__global__ void proxyNormKernel(const float* __restrict__ P) {
    int warp = (blockIdx.x * blockDim.x + threadIdx.x) >> 5;
    int lane = threadIdx.x & 31;
    if (warp >= C_SZ) return;
    const float4* p4 = (const float4*)(P + (size_t)warp * E_SZ);
    float4 v[4];
    float s = 0.0f;
#pragma unroll
    for (int j = 0; j < 4; j++) {
        v[j] = p4[lane + j * 32];
        s += v[j].x * v[j].x + v[j].y * v[j].y + v[j].z * v[j].z + v[j].w * v[j].w;
    }
#pragma unroll
    for (int o = 16; o > 0; o >>= 1) s += __shfl_xor_sync(0xffffffffu, s, o);
    float rn = rsqrtf(s + 1e-12f);
    __nv_bfloat162* out = (__nv_bfloat162*)(g_proxyB + (size_t)warp * E_SZ);
#pragma unroll
    for (int j = 0; j < 4; j++) {
        out[(lane + j * 32) * 2]     = __floats2bfloat162_rn(v[j].x * rn, v[j].y * rn);
        out[(lane + j * 32) * 2 + 1] = __floats2bfloat162_rn(v[j].z * rn, v[j].w * rn);
    }
}

// ---------------- fused GEMM (bf16 mma.sync) + epilogue ----------------
__device__ __forceinline__ void mma16816(float* d, const uint32_t* a, const uint32_t* b) {
    asm volatile(
        "mma.sync.aligned.m16n8k16.row.col.f32.bf16.bf16.f32 "
        "{%0,%1,%2,%3}, {%4,%5,%6,%7}, {%8,%9}, {%0,%1,%2,%3};\n"
        : "+f"(d[0]), "+f"(d[1]), "+f"(d[2]), "+f"(d[3])
        : "r"(a[0]), "r"(a[1]), "r"(a[2]), "r"(a[3]), "r"(b[0]), "r"(b[1]));
}

__global__ void __launch_bounds__(256) mainKernel(const int* __restrict__ targets) {
    __shared__ __align__(16) char shBuf[33280];   // GEMM bufs (30.7KB) / cos tile (33.3KB) / reductions
    __shared__ int   shTgt[BM];
    __shared__ float shOutl[BN], shIE[BN];

    __nv_bfloat16* shA = (__nv_bfloat16*)shBuf;                       // [2][BM][SA]
    __nv_bfloat16* shB = (__nv_bfloat16*)(shBuf + 2 * BM * SA * 2);   // [2][BN][SA]

    const int tid = threadIdx.x;
    const int lane = tid & 31;
    const int warp = tid >> 5;
    const int warpM = warp >> 1;   // 0..3
    const int warpN = warp & 1;    // 0..1
    const int cBase = blockIdx.x * BN;
    const int rBase = blockIdx.y * BM;

    if (tid < BM) shTgt[tid] = targets[rBase + tid];
    if (tid < BN) { shOutl[tid] = g_outlier[cBase + tid]; shIE[tid] = g_invEff[cBase + tid]; }

    float acc[2][4][4] = {};

    // initial chunk -> buffer 0
    {
#pragma unroll
        for (int j = 0; j < 2; j++) {
            int idx = tid + j * 256;
            int r = idx >> 2, s = idx & 3;
            uint4 v = *(const uint4*)(g_inputB + (size_t)(rBase + r) * E_SZ + s * 8);
            *(uint4*)(shA + (size_t)r * SA + s * 8) = v;
        }
        int r = tid >> 2, s = tid & 3;
        uint4 v = *(const uint4*)(g_proxyB + (size_t)(cBase + r) * E_SZ + s * 8);
        *(uint4*)(shB + (size_t)r * SA + s * 8) = v;
    }
    __syncthreads();

    const int NCH = E_SZ / BK;   // 16
    for (int ch = 0; ch < NCH; ch++) {
        int cur = ch & 1;
        uint4 pa0, pa1, pb;
        if (ch < NCH - 1) {
            int kOff = (ch + 1) * BK;
            { int r = tid >> 2, s = tid & 3;
              pa0 = *(const uint4*)(g_inputB + (size_t)(rBase + r) * E_SZ + kOff + s * 8); }
            { int idx = tid + 256; int r = idx >> 2, s = idx & 3;
              pa1 = *(const uint4*)(g_inputB + (size_t)(rBase + r) * E_SZ + kOff + s * 8); }
            { int r = tid >> 2, s = tid & 3;
              pb  = *(const uint4*)(g_proxyB + (size_t)(cBase + r) * E_SZ + kOff + s * 8); }
        }

        const __nv_bfloat16* Ab = shA + (size_t)cur * BM * SA;
        const __nv_bfloat16* Bb = shB + (size_t)cur * BN * SA;
#pragma unroll
        for (int ks = 0; ks < 2; ks++) {
            int c0 = ks * 16 + (lane & 3) * 2;
            uint32_t a[2][4], b[4][2];
#pragma unroll
            for (int mt = 0; mt < 2; mt++) {
                int r0 = warpM * 32 + mt * 16 + (lane >> 2);
                const __nv_bfloat16* base = Ab + (size_t)r0 * SA + c0;
                a[mt][0] = *(const uint32_t*)(base);
                a[mt][1] = *(const uint32_t*)(base + 8 * SA);
                a[mt][2] = *(const uint32_t*)(base + 8);
                a[mt][3] = *(const uint32_t*)(base + 8 * SA + 8);
            }
#pragma unroll
            for (int nt = 0; nt < 4; nt++) {
                int n0 = warpN * 32 + nt * 8 + (lane >> 2);
                const __nv_bfloat16* base = Bb + (size_t)n0 * SA + c0;
                b[nt][0] = *(const uint32_t*)(base);
                b[nt][1] = *(const uint32_t*)(base + 8);
            }
#pragma unroll
            for (int mt = 0; mt < 2; mt++)
#pragma unroll
                for (int nt = 0; nt < 4; nt++)
                    mma16816(acc[mt][nt], a[mt], b[nt]);
        }

        if (ch < NCH - 1) {
            int nb = cur ^ 1;
            __nv_bfloat16* An = shA + (size_t)nb * BM * SA;
            __nv_bfloat16* Bn = shB + (size_t)nb * BN * SA;
            { int r = tid >> 2, s = tid & 3; *(uint4*)(An + (size_t)r * SA + s * 8) = pa0; }
            { int idx = tid + 256; int r = idx >> 2, s = idx & 3;
              *(uint4*)(An + (size_t)r * SA + s * 8) = pa1; }
            { int r = tid >> 2, s = tid & 3; *(uint4*)(Bn + (size_t)r * SA + s * 8) = pb; }
        }
        __syncthreads();
    }

    // stage cos tile to smem (reuse shBuf; GEMM reads are done, synced above)
    float* cosS = (float*)shBuf;   // [BM][65]
#pragma unroll
    for (int mt = 0; mt < 2; mt++)
#pragma unroll
        for (int nt = 0; nt < 4; nt++) {
            int r0 = warpM * 32 + mt * 16 + (lane >> 2);
            int c0 = warpN * 32 + nt * 8 + (lane & 3) * 2;
            cosS[r0 * 65 + c0]           = acc[mt][nt][0];
            cosS[r0 * 65 + c0 + 1]       = acc[mt][nt][1];
            cosS[(r0 + 8) * 65 + c0]     = acc[mt][nt][2];
            cosS[(r0 + 8) * 65 + c0 + 1] = acc[mt][nt][3];
        }
    __syncthreads();

    // epilogue: per-column (class) partial sums over this CTA's 128 rows
    int col = tid & 63;
    int seg = tid >> 6;   // 0..3, 32 rows each
    int cls = cBase + col;
    float outl = shOutl[col], ie = shIE[col];
    float sP = 0.0f, sN = 0.0f, sV = 0.0f;
#pragma unroll 4
    for (int r8 = 0; r8 < 32; r8++) {
        int r = seg * 32 + r8;
        float cv = cosS[r * 65 + col];
        if (shTgt[r] == cls) {
            sP += fexp(32.0f * (0.1f - cv));
        } else {
            float nv = (cv < outl) ? ie : 1.0f;
            sV += nv;
            sN += fexp(32.0f * (cv + 0.1f) * nv);
        }
    }
    __syncthreads();   // all cos reads done; safe to reuse shBuf
    float* red = (float*)shBuf;
    red[tid] = sP; red[256 + tid] = sN; red[512 + tid] = sV;
    __syncthreads();
    if (tid < 64) {
        float p = red[tid] + red[tid + 64] + red[tid + 128] + red[tid + 192];
        float n = red[256 + tid] + red[320 + tid] + red[384 + tid] + red[448 + tid];
        float v = red[512 + tid] + red[576 + tid] + red[640 + tid] + red[704 + tid];
        atomicAdd(&g_Spos[cBase + tid], p);
        atomicAdd(&g_Sneg[cBase + tid], n);
        atomicAdd(&g_Nsum[cBase + tid], v);
    }
}

// ---------------- finalize ----------------
__global__ void finalizeKernel(float* __restrict__ out) {
    __shared__ float sm[4][256];
    int tid = threadIdx.x;
    float posT = 0.0f, negT = 0.0f, posW = 0.0f, negW = 0.0f;
    for (int c = tid; c < C_SZ; c += 256) {
        int cnt = g_cnt[c];
        if (cnt > 0) { posW += 1.0f; posT += log1pf(g_Spos[c]); }
        negT += log1pf(g_Sneg[c]);
        int Ncnt = B_SZ - cnt;
        float nm = g_Nsum[c] / fmaxf((float)Ncnt, 1.0f);
        if (Ncnt > 0) negW += nm;
    }
    sm[0][tid] = posT; sm[1][tid] = negT; sm[2][tid] = posW; sm[3][tid] = negW;
    __syncthreads();
    for (int s = 128; s > 0; s >>= 1) {
        if (tid < s) {
#pragma unroll
            for (int j = 0; j < 4; j++) sm[j][tid] += sm[j][tid + s];
        }
        __syncthreads();
    }
    if (tid == 0) out[0] = sm[0][0] / sm[2][0] + sm[1][0] / sm[3][0];
}

// ---------------- launch ----------------
extern "C" void kernel_launch(void* const* d_in, const int* in_sizes, int n_in,
                              void* d_out, int out_size) {
    const float* inputs  = (const float*)d_in[0];   // [B,E] f32
    const int*   targets = (const int*)d_in[1];     // [B]   i32
    const float* proxies = (const float*)d_in[2];   // [C,E] f32
    const float* effN    = (const float*)d_in[3];   // [C]
    const float* ls      = (const float*)d_in[4];   // [C]
    float* out = (float*)d_out;

    initKernel<<<C_SZ / 256, 256>>>(effN, ls);
    cntKernel<<<(B_SZ + 255) / 256, 256>>>(targets);
    convInputKernel<<<(B_SZ * E_SZ / 4) / 256, 256>>>(inputs);
    proxyNormKernel<<<C_SZ / 8, 256>>>(proxies);
    mainKernel<<<dim3(C_SZ / BN, B_SZ / BM), 256>>>(targets);
    finalizeKernel<<<1, 256>>>(out);
}

// round 3
// speedup vs baseline: 1.1554x; 1.1554x over previous
#include <cuda_runtime.h>
#include <cuda_bf16.h>
#include <cstdint>

#define B_SZ 1024
#define E_SZ 512
#define C_SZ 16384

// ---------------- scratch (static device memory; no runtime alloc) ----------------
__device__ __nv_bfloat16 g_proxyB[C_SZ * E_SZ];   // normalized proxies, bf16
__device__ __nv_bfloat16 g_inputB[B_SZ * E_SZ];   // inputs, bf16
__device__ float g_outlier[C_SZ];
__device__ float g_invEff[C_SZ];
__device__ int   g_cnt[C_SZ];
__device__ float g_Spos[C_SZ];
__device__ float g_Sneg[C_SZ];
__device__ float g_Nsum[C_SZ];

// ---------------- fast exp on FMA pipe ----------------
__device__ __forceinline__ float fexp(float x) {
    float t = x * 1.44269504088896341f;
    float fi = rintf(t);
    float f = t - fi;
    float p = 1.54035303933816e-4f;
    p = fmaf(p, f, 1.33335581467049e-3f);
    p = fmaf(p, f, 9.61812910762848e-3f);
    p = fmaf(p, f, 5.55041086648216e-2f);
    p = fmaf(p, f, 2.40226506959101e-1f);
    p = fmaf(p, f, 6.93147180559945e-1f);
    p = fmaf(p, f, 1.0f);
    int i = (int)fi;
    float s = __int_as_float((i + 127) << 23);
    return p * s;
}

// ---------------- prep kernels ----------------
__global__ void initKernel(const float* __restrict__ effN, const float* __restrict__ ls) {
    int c = blockIdx.x * blockDim.x + threadIdx.x;
    if (c >= C_SZ) return;
    float eff = effN[c], l = ls[c];
    float wb = 1.0f / (1.0f + log1pf(eff));
    float eta = (1.0f + (1.0f - l)) * wb + 0.1f;   // K=1, LAM=0.1
    g_outlier[c] = l - eta;
    g_invEff[c] = 1.0f / fmaxf(1.0f, eff);
    g_cnt[c] = 0;
    g_Spos[c] = 0.0f;
    g_Sneg[c] = 0.0f;
    g_Nsum[c] = 0.0f;
}

__global__ void cntKernel(const int* __restrict__ t) {
    int i = blockIdx.x * blockDim.x + threadIdx.x;
    if (i < B_SZ) atomicAdd(&g_cnt[t[i]], 1);
}

__global__ void convInputKernel(const float* __restrict__ in) {
    int i = blockIdx.x * blockDim.x + threadIdx.x;   // over B*E/4 float4s
    float4 v = ((const float4*)in)[i];
    __nv_bfloat162* o = (__nv_bfloat162*)g_inputB;
    o[i * 2]     = __floats2bfloat162_rn(v.x, v.y);
    o[i * 2 + 1] = __floats2bfloat162_rn(v.z, v.w);
}

__global__ void proxyNormKernel(const float* __restrict__ P) {
    int warp = (blockIdx.x * blockDim.x + threadIdx.x) >> 5;
    int lane = threadIdx.x & 31;
    if (warp >= C_SZ) return;
    const float4* p4 = (const float4*)(P + (size_t)warp * E_SZ);
    float4 v[4];
    float s = 0.0f;
#pragma unroll
    for (int j = 0; j < 4; j++) {
        v[j] = p4[lane + j * 32];
        s += v[j].x * v[j].x + v[j].y * v[j].y + v[j].z * v[j].z + v[j].w * v[j].w;
    }
#pragma unroll
    for (int o = 16; o > 0; o >>= 1) s += __shfl_xor_sync(0xffffffffu, s, o);
    float rn = rsqrtf(s + 1e-12f);
    __nv_bfloat162* out = (__nv_bfloat162*)(g_proxyB + (size_t)warp * E_SZ);
#pragma unroll
    for (int j = 0; j < 4; j++) {
        out[(lane + j * 32) * 2]     = __floats2bfloat162_rn(v[j].x * rn, v[j].y * rn);
        out[(lane + j * 32) * 2 + 1] = __floats2bfloat162_rn(v[j].z * rn, v[j].w * rn);
    }
}

// ---------------- HMMA helpers ----------------
__device__ __forceinline__ uint32_t smem_u32(const void* p) {
    uint32_t a;
    asm("{ .reg .u64 t; cvta.to.shared.u64 t, %1; cvt.u32.u64 %0, t; }" : "=r"(a) : "l"(p));
    return a;
}
__device__ __forceinline__ void mma16816(float* d, const uint32_t* a, const uint32_t* b) {
    asm volatile(
        "mma.sync.aligned.m16n8k16.row.col.f32.bf16.bf16.f32 "
        "{%0,%1,%2,%3}, {%4,%5,%6,%7}, {%8,%9}, {%0,%1,%2,%3};\n"
        : "+f"(d[0]), "+f"(d[1]), "+f"(d[2]), "+f"(d[3])
        : "r"(a[0]), "r"(a[1]), "r"(a[2]), "r"(a[3]), "r"(b[0]), "r"(b[1]));
}
#define LDSM_X4(r, a) \
    asm volatile("ldmatrix.sync.aligned.m8n8.x4.shared.b16 {%0,%1,%2,%3}, [%4];" \
        : "=r"((r)[0]), "=r"((r)[1]), "=r"((r)[2]), "=r"((r)[3]) : "r"(a))

__device__ __forceinline__ void cpa16(uint32_t s, const void* g) {
    asm volatile("cp.async.cg.shared.global [%0], [%1], 16;" :: "r"(s), "l"(g));
}
#define CP_COMMIT() asm volatile("cp.async.commit_group;" ::: "memory")

// row r (128B rows), 16B granule g (0..7): xor swizzle
#define SWZ(r, g) ((r) * 128 + (((g) ^ ((r) & 7)) << 4))

// ---------------- main HMMA kernel ----------------
// CTA tile: M=256 x N=128, K chunks of 64 (8 chunks), double buffered.
// 256 threads = 8 warps, warp grid 4(M) x 2(N): warp tile 64x64.
#define SM_TGT  0       // 256 ints
#define SM_OUTL 1024    // 128 floats
#define SM_IE   1536    // 128 floats
#define SM_A    2048    // 2 x 32768 (256 rows x 128B)
#define SM_B    67584   // 2 x 16384 (128 rows x 128B)
#define SM_BYTES 100352

__global__ void __launch_bounds__(256, 1) mainHMMA(const int* __restrict__ targets) {
    extern __shared__ __align__(1024) char sm[];
    const uint32_t smb = smem_u32(sm);
    const int tid = threadIdx.x;
    const int lane = tid & 31;
    const int warp = tid >> 5;
    const int warpM = warp >> 1;   // 0..3  (64 rows each)
    const int warpN = warp & 1;    // 0..1  (64 cols each)
    const int cBase = blockIdx.x * 128;
    const int mBase = blockIdx.y * 256;

    // stage per-row / per-class constants
    ((int*)(sm + SM_TGT))[tid] = targets[mBase + tid];
    if (tid < 128) {
        ((float*)(sm + SM_OUTL))[tid] = g_outlier[cBase + tid];
        ((float*)(sm + SM_IE))[tid]   = g_invEff[cBase + tid];
    }

    float acc[4][8][4];
#pragma unroll
    for (int i = 0; i < 4; i++)
#pragma unroll
        for (int j = 0; j < 8; j++)
#pragma unroll
            for (int e = 0; e < 4; e++) acc[i][j][e] = 0.0f;

    // prefetch helper (inlined twice below + in loop)
#define PREFETCH(c, buf) do { \
        const int kOff = (c) * 64; \
        _Pragma("unroll") \
        for (int i = 0; i < 8; i++) { \
            int idx = tid + i * 256; int r = idx >> 3, g = idx & 7; \
            cpa16(smb + SM_A + (buf) * 32768 + SWZ(r, g), \
                  g_inputB + (size_t)(mBase + r) * E_SZ + kOff + g * 8); \
        } \
        _Pragma("unroll") \
        for (int i = 0; i < 4; i++) { \
            int idx = tid + i * 256; int r = idx >> 3, g = idx & 7; \
            cpa16(smb + SM_B + (buf) * 16384 + SWZ(r, g), \
                  g_proxyB + (size_t)(cBase + r) * E_SZ + kOff + g * 8); \
        } \
        CP_COMMIT(); \
    } while (0)

    PREFETCH(0, 0);
    PREFETCH(1, 1);

    for (int c = 0; c < 8; c++) {
        const int buf = c & 1;
        if (c < 7) { asm volatile("cp.async.wait_group 1;" ::: "memory"); }
        else       { asm volatile("cp.async.wait_group 0;" ::: "memory"); }
        __syncthreads();

        const uint32_t aBase = smb + SM_A + buf * 32768;
        const uint32_t bBase = smb + SM_B + buf * 16384;
#pragma unroll
        for (int ks = 0; ks < 4; ks++) {
            uint32_t a[4][4], b[4][4];
#pragma unroll
            for (int mt = 0; mt < 4; mt++) {
                int r = warpM * 64 + mt * 16 + (lane & 15);
                int g = ks * 2 + (lane >> 4);
                uint32_t addr = aBase + SWZ(r, g);
                LDSM_X4(a[mt], addr);
            }
#pragma unroll
            for (int np = 0; np < 4; np++) {
                int n = warpN * 64 + np * 16 + ((lane >> 4) << 3) + (lane & 7);
                int g = ks * 2 + ((lane >> 3) & 1);
                uint32_t addr = bBase + SWZ(n, g);
                LDSM_X4(b[np], addr);
            }
#pragma unroll
            for (int mt = 0; mt < 4; mt++)
#pragma unroll
                for (int nt = 0; nt < 8; nt++)
                    mma16816(acc[mt][nt], a[mt], &b[nt >> 1][(nt & 1) * 2]);
        }
        __syncthreads();
        if (c + 2 < 8) PREFETCH(c + 2, buf);
    }

    // ---- register-direct epilogue ----
    const int* shTgt = (const int*)(sm + SM_TGT);
    const float* shOutl = (const float*)(sm + SM_OUTL);
    const float* shIE = (const float*)(sm + SM_IE);

    int tg[4][2];
#pragma unroll
    for (int mt = 0; mt < 4; mt++) {
        int rl = warpM * 64 + mt * 16 + (lane >> 2);
        tg[mt][0] = shTgt[rl];
        tg[mt][1] = shTgt[rl + 8];
    }

#pragma unroll
    for (int nt = 0; nt < 8; nt++) {
#pragma unroll
        for (int p = 0; p < 2; p++) {
            int cc = warpN * 64 + nt * 8 + (lane & 3) * 2 + p;
            float outl = shOutl[cc];
            float ie = shIE[cc];
            int clsG = cBase + cc;
            float sP = 0.0f, sN = 0.0f, sV = 0.0f;
#pragma unroll
            for (int mt = 0; mt < 4; mt++) {
#pragma unroll
                for (int h = 0; h < 2; h++) {
                    float cv = acc[mt][nt][h * 2 + p];
                    if (tg[mt][h] == clsG) {
                        sP += fexp(32.0f * (0.1f - cv));
                    } else {
                        float nv = (cv < outl) ? ie : 1.0f;
                        sV += nv;
                        sN += fexp(32.0f * (cv + 0.1f) * nv);
                    }
                }
            }
#pragma unroll
            for (int o = 4; o <= 16; o <<= 1) {
                sP += __shfl_xor_sync(0xffffffffu, sP, o);
                sN += __shfl_xor_sync(0xffffffffu, sN, o);
                sV += __shfl_xor_sync(0xffffffffu, sV, o);
            }
            if ((lane >> 2) == 0) {
                atomicAdd(&g_Spos[clsG], sP);
                atomicAdd(&g_Sneg[clsG], sN);
                atomicAdd(&g_Nsum[clsG], sV);
            }
        }
    }
}

// ---------------- finalize ----------------
__global__ void finalizeKernel(float* __restrict__ out) {
    __shared__ float smr[4][256];
    int tid = threadIdx.x;
    float posT = 0.0f, negT = 0.0f, posW = 0.0f, negW = 0.0f;
    for (int c = tid; c < C_SZ; c += 256) {
        int cnt = g_cnt[c];
        if (cnt > 0) { posW += 1.0f; posT += log1pf(g_Spos[c]); }
        negT += log1pf(g_Sneg[c]);
        int Ncnt = B_SZ - cnt;
        float nm = g_Nsum[c] / fmaxf((float)Ncnt, 1.0f);
        if (Ncnt > 0) negW += nm;
    }
    smr[0][tid] = posT; smr[1][tid] = negT; smr[2][tid] = posW; smr[3][tid] = negW;
    __syncthreads();
    for (int s = 128; s > 0; s >>= 1) {
        if (tid < s) {
#pragma unroll
            for (int j = 0; j < 4; j++) smr[j][tid] += smr[j][tid + s];
        }
        __syncthreads();
    }
    if (tid == 0) out[0] = smr[0][0] / smr[2][0] + smr[1][0] / smr[3][0];
}

// ---------------- launch ----------------
extern "C" void kernel_launch(void* const* d_in, const int* in_sizes, int n_in,
                              void* d_out, int out_size) {
    const float* inputs  = (const float*)d_in[0];   // [B,E] f32
    const int*   targets = (const int*)d_in[1];     // [B]   i32
    const float* proxies = (const float*)d_in[2];   // [C,E] f32
    const float* effN    = (const float*)d_in[3];   // [C]
    const float* ls      = (const float*)d_in[4];   // [C]
    float* out = (float*)d_out;

    cudaFuncSetAttribute(mainHMMA, cudaFuncAttributeMaxDynamicSharedMemorySize, SM_BYTES);

    initKernel<<<C_SZ / 256, 256>>>(effN, ls);
    cntKernel<<<(B_SZ + 255) / 256, 256>>>(targets);
    convInputKernel<<<(B_SZ * E_SZ / 4) / 256, 256>>>(inputs);
    proxyNormKernel<<<C_SZ / 8, 256>>>(proxies);
    mainHMMA<<<dim3(C_SZ / 128, B_SZ / 256), 256, SM_BYTES>>>(targets);
    finalizeKernel<<<1, 256>>>(out);
}

// round 4
// speedup vs baseline: 1.4213x; 1.2302x over previous
#include <cuda_runtime.h>
#include <cuda_bf16.h>
#include <cstdint>

#define B_SZ 1024
#define E_SZ 512
#define C_SZ 16384

// ---------------- scratch (static device memory; no runtime alloc) ----------------
__device__ __nv_bfloat16 g_proxyB[C_SZ * E_SZ];   // normalized proxies, bf16
__device__ __nv_bfloat16 g_inputB[B_SZ * E_SZ];   // inputs, bf16
__device__ float g_outlier[C_SZ];
__device__ float g_invEff[C_SZ];
__device__ int   g_cnt[C_SZ];
__device__ float g_Spos[C_SZ];
__device__ float g_Sneg[C_SZ];
__device__ float g_Nsum[C_SZ];

// ---------------- fast exp on FMA pipe ----------------
__device__ __forceinline__ float fexp(float x) {
    float t = x * 1.44269504088896341f;
    float fi = rintf(t);
    float f = t - fi;
    float p = 1.54035303933816e-4f;
    p = fmaf(p, f, 1.33335581467049e-3f);
    p = fmaf(p, f, 9.61812910762848e-3f);
    p = fmaf(p, f, 5.55041086648216e-2f);
    p = fmaf(p, f, 2.40226506959101e-1f);
    p = fmaf(p, f, 6.93147180559945e-1f);
    p = fmaf(p, f, 1.0f);
    int i = (int)fi;
    float s = __int_as_float((i + 127) << 23);
    return p * s;
}

// ---------------- prep kernels ----------------
__global__ void initKernel(const float* __restrict__ effN, const float* __restrict__ ls) {
    int c = blockIdx.x * blockDim.x + threadIdx.x;
    if (c >= C_SZ) return;
    float eff = effN[c], l = ls[c];
    float wb = 1.0f / (1.0f + log1pf(eff));
    float eta = (1.0f + (1.0f - l)) * wb + 0.1f;   // K=1, LAM=0.1
    g_outlier[c] = l - eta;
    g_invEff[c] = 1.0f / fmaxf(1.0f, eff);
    g_cnt[c] = 0;
    g_Spos[c] = 0.0f;
    g_Sneg[c] = 0.0f;
    g_Nsum[c] = 0.0f;
}

__global__ void cntKernel(const int* __restrict__ t) {
    int i = blockIdx.x * blockDim.x + threadIdx.x;
    if (i < B_SZ) atomicAdd(&g_cnt[t[i]], 1);
}

__global__ void convInputKernel(const float* __restrict__ in) {
    int i = blockIdx.x * blockDim.x + threadIdx.x;   // over B*E/4 float4s
    float4 v = ((const float4*)in)[i];
    __nv_bfloat162* o = (__nv_bfloat162*)g_inputB;
    o[i * 2]     = __floats2bfloat162_rn(v.x, v.y);
    o[i * 2 + 1] = __floats2bfloat162_rn(v.z, v.w);
}

__global__ void proxyNormKernel(const float* __restrict__ P) {
    int warp = (blockIdx.x * blockDim.x + threadIdx.x) >> 5;
    int lane = threadIdx.x & 31;
    if (warp >= C_SZ) return;
    const float4* p4 = (const float4*)(P + (size_t)warp * E_SZ);
    float4 v[4];
    float s = 0.0f;
#pragma unroll
    for (int j = 0; j < 4; j++) {
        v[j] = p4[lane + j * 32];
        s += v[j].x * v[j].x + v[j].y * v[j].y + v[j].z * v[j].z + v[j].w * v[j].w;
    }
#pragma unroll
    for (int o = 16; o > 0; o >>= 1) s += __shfl_xor_sync(0xffffffffu, s, o);
    float rn = rsqrtf(s + 1e-12f);
    __nv_bfloat162* out = (__nv_bfloat162*)(g_proxyB + (size_t)warp * E_SZ);
#pragma unroll
    for (int j = 0; j < 4; j++) {
        out[(lane + j * 32) * 2]     = __floats2bfloat162_rn(v[j].x * rn, v[j].y * rn);
        out[(lane + j * 32) * 2 + 1] = __floats2bfloat162_rn(v[j].z * rn, v[j].w * rn);
    }
}

// ---------------- HMMA helpers ----------------
__device__ __forceinline__ uint32_t smem_u32(const void* p) {
    uint32_t a;
    asm("{ .reg .u64 t; cvta.to.shared.u64 t, %1; cvt.u32.u64 %0, t; }" : "=r"(a) : "l"(p));
    return a;
}
__device__ __forceinline__ void mma16816(float* d, const uint32_t* a, const uint32_t* b) {
    asm volatile(
        "mma.sync.aligned.m16n8k16.row.col.f32.bf16.bf16.f32 "
        "{%0,%1,%2,%3}, {%4,%5,%6,%7}, {%8,%9}, {%0,%1,%2,%3};\n"
        : "+f"(d[0]), "+f"(d[1]), "+f"(d[2]), "+f"(d[3])
        : "r"(a[0]), "r"(a[1]), "r"(a[2]), "r"(a[3]), "r"(b[0]), "r"(b[1]));
}
#define LDSM_X4(r, a) \
    asm volatile("ldmatrix.sync.aligned.m8n8.x4.shared.b16 {%0,%1,%2,%3}, [%4];" \
        : "=r"((r)[0]), "=r"((r)[1]), "=r"((r)[2]), "=r"((r)[3]) : "r"(a))

__device__ __forceinline__ void cpa16(uint32_t s, const void* g) {
    asm volatile("cp.async.cg.shared.global [%0], [%1], 16;" :: "r"(s), "l"(g));
}
#define CP_COMMIT() asm volatile("cp.async.commit_group;" ::: "memory")

// row r (128B rows), 16B granule g (0..7): xor swizzle
#define SWZ(r, g) ((r) * 128 + (((g) ^ ((r) & 7)) << 4))

// ---------------- main HMMA kernel ----------------
// CTA tile: M=128 x N=128, K chunks of 64 (8 chunks), 3-stage cp.async ring.
// 256 threads = 8 warps, warp grid 2(M) x 4(N): warp tile 64x32.
// 2 CTAs / SM (regs<=128, smem 98KB).
#define SM_TGT  0       // 128 ints
#define SM_OUTL 512     // 128 floats
#define SM_IE   1024    // 128 floats
#define SM_A    2048    // 3 x 16384 (128 rows x 128B)
#define SM_B    51200   // 3 x 16384
#define SM_BYTES 100352

__global__ void __launch_bounds__(256, 2) mainHMMA(const int* __restrict__ targets) {
    extern __shared__ __align__(1024) char sm[];
    const uint32_t smb = smem_u32(sm);
    const int tid = threadIdx.x;
    const int lane = tid & 31;
    const int warp = tid >> 5;
    const int warpM = warp >> 2;   // 0..1 (64 rows each)
    const int warpN = warp & 3;    // 0..3 (32 cols each)
    const int cBase = blockIdx.x * 128;
    const int mBase = blockIdx.y * 128;

    // stage per-row / per-class constants
    if (tid < 128) {
        ((int*)(sm + SM_TGT))[tid]    = targets[mBase + tid];
        ((float*)(sm + SM_OUTL))[tid] = g_outlier[cBase + tid];
        ((float*)(sm + SM_IE))[tid]   = g_invEff[cBase + tid];
    }

    float acc[4][4][4];
#pragma unroll
    for (int i = 0; i < 4; i++)
#pragma unroll
        for (int j = 0; j < 4; j++)
#pragma unroll
            for (int e = 0; e < 4; e++) acc[i][j][e] = 0.0f;

    // prefetch one K-chunk (64 cols) of A(128 rows) + B(128 rows) into a stage
#define PREFETCH(c, stg) do { \
        const int kOff = (c) * 64; \
        _Pragma("unroll") \
        for (int i = 0; i < 4; i++) { \
            int idx = tid + i * 256; int r = idx >> 3, g = idx & 7; \
            cpa16(smb + SM_A + (stg) * 16384 + SWZ(r, g), \
                  g_inputB + (size_t)(mBase + r) * E_SZ + kOff + g * 8); \
        } \
        _Pragma("unroll") \
        for (int i = 0; i < 4; i++) { \
            int idx = tid + i * 256; int r = idx >> 3, g = idx & 7; \
            cpa16(smb + SM_B + (stg) * 16384 + SWZ(r, g), \
                  g_proxyB + (size_t)(cBase + r) * E_SZ + kOff + g * 8); \
        } \
        CP_COMMIT(); \
    } while (0)

    PREFETCH(0, 0);
    PREFETCH(1, 1);
    PREFETCH(2, 2);

    int stg = 0;
#pragma unroll 1
    for (int c = 0; c < 8; c++) {
        if (c < 6)      { asm volatile("cp.async.wait_group 2;" ::: "memory"); }
        else if (c == 6){ asm volatile("cp.async.wait_group 1;" ::: "memory"); }
        else            { asm volatile("cp.async.wait_group 0;" ::: "memory"); }
        __syncthreads();

        const uint32_t aBase = smb + SM_A + stg * 16384;
        const uint32_t bBase = smb + SM_B + stg * 16384;
#pragma unroll
        for (int ks = 0; ks < 4; ks++) {
            uint32_t a[4][4], b[2][4];
#pragma unroll
            for (int mt = 0; mt < 4; mt++) {
                int r = warpM * 64 + mt * 16 + (lane & 15);
                int g = ks * 2 + (lane >> 4);
                LDSM_X4(a[mt], aBase + SWZ(r, g));
            }
#pragma unroll
            for (int np = 0; np < 2; np++) {
                int n = warpN * 32 + np * 16 + ((lane >> 4) << 3) + (lane & 7);
                int g = ks * 2 + ((lane >> 3) & 1);
                LDSM_X4(b[np], bBase + SWZ(n, g));
            }
#pragma unroll
            for (int mt = 0; mt < 4; mt++)
#pragma unroll
                for (int nt = 0; nt < 4; nt++)
                    mma16816(acc[mt][nt], a[mt], &b[nt >> 1][(nt & 1) * 2]);
        }
        __syncthreads();
        if (c + 3 < 8) PREFETCH(c + 3, stg);
        stg = (stg == 2) ? 0 : stg + 1;
    }

    // ---- register-direct epilogue ----
    const int* shTgt = (const int*)(sm + SM_TGT);
    const float* shOutl = (const float*)(sm + SM_OUTL);
    const float* shIE = (const float*)(sm + SM_IE);

    int tg[4][2];
#pragma unroll
    for (int mt = 0; mt < 4; mt++) {
        int rl = warpM * 64 + mt * 16 + (lane >> 2);
        tg[mt][0] = shTgt[rl];
        tg[mt][1] = shTgt[rl + 8];
    }

#pragma unroll
    for (int nt = 0; nt < 4; nt++) {
#pragma unroll
        for (int p = 0; p < 2; p++) {
            int cc = warpN * 32 + nt * 8 + (lane & 3) * 2 + p;
            float outl = shOutl[cc];
            float ie = shIE[cc];
            int clsG = cBase + cc;
            float sP = 0.0f, sN = 0.0f, sV = 0.0f;
#pragma unroll
            for (int mt = 0; mt < 4; mt++) {
#pragma unroll
                for (int h = 0; h < 2; h++) {
                    float cv = acc[mt][nt][h * 2 + p];
                    if (tg[mt][h] == clsG) {
                        sP += fexp(32.0f * (0.1f - cv));
                    } else {
                        float nv = (cv < outl) ? ie : 1.0f;
                        sV += nv;
                        sN += fexp(32.0f * (cv + 0.1f) * nv);
                    }
                }
            }
#pragma unroll
            for (int o = 4; o <= 16; o <<= 1) {
                sP += __shfl_xor_sync(0xffffffffu, sP, o);
                sN += __shfl_xor_sync(0xffffffffu, sN, o);
                sV += __shfl_xor_sync(0xffffffffu, sV, o);
            }
            if ((lane >> 2) == 0) {
                atomicAdd(&g_Spos[clsG], sP);
                atomicAdd(&g_Sneg[clsG], sN);
                atomicAdd(&g_Nsum[clsG], sV);
            }
        }
    }
}

// ---------------- finalize ----------------
__global__ void finalizeKernel(float* __restrict__ out) {
    __shared__ float smr[4][256];
    int tid = threadIdx.x;
    float posT = 0.0f, negT = 0.0f, posW = 0.0f, negW = 0.0f;
    for (int c = tid; c < C_SZ; c += 256) {
        int cnt = g_cnt[c];
        if (cnt > 0) { posW += 1.0f; posT += log1pf(g_Spos[c]); }
        negT += log1pf(g_Sneg[c]);
        int Ncnt = B_SZ - cnt;
        float nm = g_Nsum[c] / fmaxf((float)Ncnt, 1.0f);
        if (Ncnt > 0) negW += nm;
    }
    smr[0][tid] = posT; smr[1][tid] = negT; smr[2][tid] = posW; smr[3][tid] = negW;
    __syncthreads();
    for (int s = 128; s > 0; s >>= 1) {
        if (tid < s) {
#pragma unroll
            for (int j = 0; j < 4; j++) smr[j][tid] += smr[j][tid + s];
        }
        __syncthreads();
    }
    if (tid == 0) out[0] = smr[0][0] / smr[2][0] + smr[1][0] / smr[3][0];
}

// ---------------- launch ----------------
extern "C" void kernel_launch(void* const* d_in, const int* in_sizes, int n_in,
                              void* d_out, int out_size) {
    const float* inputs  = (const float*)d_in[0];   // [B,E] f32
    const int*   targets = (const int*)d_in[1];     // [B]   i32
    const float* proxies = (const float*)d_in[2];   // [C,E] f32
    const float* effN    = (const float*)d_in[3];   // [C]
    const float* ls      = (const float*)d_in[4];   // [C]
    float* out = (float*)d_out;

    cudaFuncSetAttribute(mainHMMA, cudaFuncAttributeMaxDynamicSharedMemorySize, SM_BYTES);

    initKernel<<<C_SZ / 256, 256>>>(effN, ls);
    cntKernel<<<(B_SZ + 255) / 256, 256>>>(targets);
    convInputKernel<<<(B_SZ * E_SZ / 4) / 256, 256>>>(inputs);
    proxyNormKernel<<<C_SZ / 8, 256>>>(proxies);
    mainHMMA<<<dim3(C_SZ / 128, B_SZ / 128), 256, SM_BYTES>>>(targets);
    finalizeKernel<<<1, 256>>>(out);
}

// round 6
// speedup vs baseline: 1.9755x; 1.3899x over previous
#include <cuda_runtime.h>
#include <cuda_bf16.h>
#include <cstdint>

#define B_SZ 1024
#define E_SZ 512
#define C_SZ 16384

// ---------------- scratch (static device memory; no runtime alloc) ----------------
__device__ __nv_bfloat16 g_proxyB[C_SZ * E_SZ];   // normalized proxies, bf16
__device__ __nv_bfloat16 g_inputB[B_SZ * E_SZ];   // inputs, bf16
__device__ float g_outlier[C_SZ];
__device__ float g_invEff[C_SZ];
__device__ float g_Spos[C_SZ];
__device__ float g_Sneg[C_SZ];
__device__ float g_Nsum[C_SZ];

// ---------------- fast exp on FMA pipe ----------------
__device__ __forceinline__ float fexp(float x) {
    float t = x * 1.44269504088896341f;
    float fi = rintf(t);
    float f = t - fi;
    float p = 1.54035303933816e-4f;
    p = fmaf(p, f, 1.33335581467049e-3f);
    p = fmaf(p, f, 9.61812910762848e-3f);
    p = fmaf(p, f, 5.55041086648216e-2f);
    p = fmaf(p, f, 2.40226506959101e-1f);
    p = fmaf(p, f, 6.93147180559945e-1f);
    p = fmaf(p, f, 1.0f);
    int i = (int)fi;
    float s = __int_as_float((i + 127) << 23);
    return p * s;
}

// ---------------- fused prep kernel (no cross-block dependencies) ----------------
// blocks 0..2047   : proxy L2-norm + bf16 (8 rows per block, 1 warp/row)
// blocks 2048..2559: input f32->bf16 (1 float4/thread)
// blocks 2560..2623: per-class constants + accumulator zero
__global__ void __launch_bounds__(256) prepKernel(
    const float* __restrict__ inputs,
    const float* __restrict__ proxies, const float* __restrict__ effN,
    const float* __restrict__ ls)
{
    const int b = blockIdx.x;
    const int tid = threadIdx.x;
    if (b < 2048) {
        int row = b * 8 + (tid >> 5);
        int lane = tid & 31;
        const float4* p4 = (const float4*)(proxies + (size_t)row * E_SZ);
        float4 v[4];
        float s = 0.0f;
#pragma unroll
        for (int j = 0; j < 4; j++) {
            v[j] = p4[lane + j * 32];
            s += v[j].x * v[j].x + v[j].y * v[j].y + v[j].z * v[j].z + v[j].w * v[j].w;
        }
#pragma unroll
        for (int o = 16; o > 0; o >>= 1) s += __shfl_xor_sync(0xffffffffu, s, o);
        float rn = rsqrtf(s + 1e-12f);
        __nv_bfloat162* out = (__nv_bfloat162*)(g_proxyB + (size_t)row * E_SZ);
#pragma unroll
        for (int j = 0; j < 4; j++) {
            out[(lane + j * 32) * 2]     = __floats2bfloat162_rn(v[j].x * rn, v[j].y * rn);
            out[(lane + j * 32) * 2 + 1] = __floats2bfloat162_rn(v[j].z * rn, v[j].w * rn);
        }
    } else if (b < 2560) {
        int i = (b - 2048) * 256 + tid;          // over B*E/4 float4s
        float4 v = ((const float4*)inputs)[i];
        __nv_bfloat162* o = (__nv_bfloat162*)g_inputB;
        o[i * 2]     = __floats2bfloat162_rn(v.x, v.y);
        o[i * 2 + 1] = __floats2bfloat162_rn(v.z, v.w);
    } else {
        int c = (b - 2560) * 256 + tid;
        float eff = effN[c], l = ls[c];
        float wb = 1.0f / (1.0f + log1pf(eff));
        float eta = (1.0f + (1.0f - l)) * wb + 0.1f;   // K=1, LAM=0.1
        g_outlier[c] = l - eta;
        g_invEff[c] = 1.0f / fmaxf(1.0f, eff);
        g_Spos[c] = 0.0f;
        g_Sneg[c] = 0.0f;
        g_Nsum[c] = 0.0f;
    }
}

// ---------------- HMMA helpers ----------------
__device__ __forceinline__ uint32_t smem_u32(const void* p) {
    uint32_t a;
    asm("{ .reg .u64 t; cvta.to.shared.u64 t, %1; cvt.u32.u64 %0, t; }" : "=r"(a) : "l"(p));
    return a;
}
__device__ __forceinline__ void mma16816(float* d, const uint32_t* a, const uint32_t* b) {
    asm volatile(
        "mma.sync.aligned.m16n8k16.row.col.f32.bf16.bf16.f32 "
        "{%0,%1,%2,%3}, {%4,%5,%6,%7}, {%8,%9}, {%0,%1,%2,%3};\n"
        : "+f"(d[0]), "+f"(d[1]), "+f"(d[2]), "+f"(d[3])
        : "r"(a[0]), "r"(a[1]), "r"(a[2]), "r"(a[3]), "r"(b[0]), "r"(b[1]));
}
#define LDSM_X4(r, a) \
    asm volatile("ldmatrix.sync.aligned.m8n8.x4.shared.b16 {%0,%1,%2,%3}, [%4];" \
        : "=r"((r)[0]), "=r"((r)[1]), "=r"((r)[2]), "=r"((r)[3]) : "r"(a))

__device__ __forceinline__ void cpa16(uint32_t s, const void* g) {
    asm volatile("cp.async.cg.shared.global [%0], [%1], 16;" :: "r"(s), "l"(g));
}
#define CP_COMMIT() asm volatile("cp.async.commit_group;" ::: "memory")

// row r (128B rows), 16B granule g (0..7): xor swizzle
#define SWZ(r, g) ((r) * 128 + (((g) ^ ((r) & 7)) << 4))

// ---------------- persistent main HMMA kernel ----------------
// Tiles: 128x128, tile id t: cBase=(t&127)*128, mBase=(t>>7)*128; 1024 tiles.
// Grid = 296 persistent CTAs (2/SM). Each CTA streams its tiles as one
// continuous K-chunk pipeline (chunk = 64 cols; 8 chunks per tile),
// 3-stage cp.async ring, prefetch distance 2, one syncthreads per chunk.
#define GRID_MAIN 296
#define NTILES    1024

#define SM_TGT   0       // int [2][128]
#define SM_OUTL  1024    // float [2][128]
#define SM_IE    2048    // float [2][128]
#define SM_STG   3072    // 3 stages x (A 16KB + B 16KB)
#define SM_BYTES 101376

__global__ void __launch_bounds__(256, 2) mainHMMA(const int* __restrict__ targets) {
    extern __shared__ __align__(1024) char sm[];
    const uint32_t smb = smem_u32(sm);
    const int tid = threadIdx.x;
    const int lane = tid & 31;
    const int warp = tid >> 5;
    const int warpM = warp >> 2;   // 0..1 (64 rows each)
    const int warpN = warp & 3;    // 0..3 (32 cols each)
    const int bid = blockIdx.x;

    const int NT = (NTILES - bid + GRID_MAIN - 1) / GRID_MAIN;   // tiles this CTA
    const int NT8 = NT * 8;

    float acc[4][4][4];
#pragma unroll
    for (int i = 0; i < 4; i++)
#pragma unroll
        for (int j = 0; j < 4; j++)
#pragma unroll
            for (int e = 0; e < 4; e++) acc[i][j][e] = 0.0f;

    // prefetch global chunk gg (tile bid + (gg>>3)*296, k-chunk gg&7) into stage gg%3
#define PREFETCH(gg) do { \
        const int T_ = (gg) >> 3, k_ = (gg) & 7; \
        const int tt_ = bid + T_ * GRID_MAIN; \
        const int cB_ = (tt_ & 127) << 7, mB_ = (tt_ >> 7) << 7; \
        const int kOff_ = k_ * 64; \
        const uint32_t stg_ = smb + SM_STG + ((gg) % 3) * 32768; \
        _Pragma("unroll") \
        for (int i_ = 0; i_ < 4; i_++) { \
            int idx_ = tid + i_ * 256; int r_ = idx_ >> 3, q_ = idx_ & 7; \
            cpa16(stg_ + SWZ(r_, q_), \
                  g_inputB + (size_t)(mB_ + r_) * E_SZ + kOff_ + q_ * 8); \
        } \
        _Pragma("unroll") \
        for (int i_ = 0; i_ < 4; i_++) { \
            int idx_ = tid + i_ * 256; int r_ = idx_ >> 3, q_ = idx_ & 7; \
            cpa16(stg_ + 16384 + SWZ(r_, q_), \
                  g_proxyB + (size_t)(cB_ + r_) * E_SZ + kOff_ + q_ * 8); \
        } \
        if (k_ == 0) { \
            int par_ = (T_ & 1) << 9; \
            if (tid < 32)       cpa16(smb + SM_TGT  + par_ + tid * 16,        targets   + mB_ + tid * 4); \
            else if (tid < 64)  cpa16(smb + SM_OUTL + par_ + (tid - 32) * 16, g_outlier + cB_ + (tid - 32) * 4); \
            else if (tid < 96)  cpa16(smb + SM_IE   + par_ + (tid - 64) * 16, g_invEff  + cB_ + (tid - 64) * 4); \
        } \
        CP_COMMIT(); \
    } while (0)

    PREFETCH(0);
    if (NT8 > 1) PREFETCH(1);

#pragma unroll 1
    for (int g = 0; g < NT8; g++) {
        if (g < NT8 - 1) { asm volatile("cp.async.wait_group 1;" ::: "memory"); }
        else             { asm volatile("cp.async.wait_group 0;" ::: "memory"); }
        __syncthreads();
        if (g + 2 < NT8) PREFETCH(g + 2);

        const uint32_t aBase = smb + SM_STG + (g % 3) * 32768;
        const uint32_t bBase = aBase + 16384;
#pragma unroll
        for (int ks = 0; ks < 4; ks++) {
            uint32_t a[4][4], bfr[2][4];
#pragma unroll
            for (int mt = 0; mt < 4; mt++) {
                int r = warpM * 64 + mt * 16 + (lane & 15);
                int q = ks * 2 + (lane >> 4);
                LDSM_X4(a[mt], aBase + SWZ(r, q));
            }
#pragma unroll
            for (int np = 0; np < 2; np++) {
                int n = warpN * 32 + np * 16 + ((lane >> 4) << 3) + (lane & 7);
                int q = ks * 2 + ((lane >> 3) & 1);
                LDSM_X4(bfr[np], bBase + SWZ(n, q));
            }
#pragma unroll
            for (int mt = 0; mt < 4; mt++)
#pragma unroll
                for (int nt = 0; nt < 4; nt++)
                    mma16816(acc[mt][nt], a[mt], &bfr[nt >> 1][(nt & 1) * 2]);
        }

        if ((g & 7) == 7) {
            // ---- epilogue for tile T = g>>3 ----
            const int T = g >> 3;
            const int tt = bid + T * GRID_MAIN;
            const int cBase = (tt & 127) << 7;
            const int par = (T & 1) << 7;
            const int* shTgt = (const int*)(sm + SM_TGT) + par;
            const float* shOutl = (const float*)(sm + SM_OUTL) + par;
            const float* shIE = (const float*)(sm + SM_IE) + par;

            int tg[4][2];
#pragma unroll
            for (int mt = 0; mt < 4; mt++) {
                int rl = warpM * 64 + mt * 16 + (lane >> 2);
                tg[mt][0] = shTgt[rl];
                tg[mt][1] = shTgt[rl + 8];
            }
#pragma unroll
            for (int nt = 0; nt < 4; nt++) {
#pragma unroll
                for (int p = 0; p < 2; p++) {
                    int cc = warpN * 32 + nt * 8 + (lane & 3) * 2 + p;
                    float outl = shOutl[cc];
                    float ie = shIE[cc];
                    int clsG = cBase + cc;
                    float sP = 0.0f, sN = 0.0f, sV = 0.0f;
#pragma unroll
                    for (int mt = 0; mt < 4; mt++) {
#pragma unroll
                        for (int h = 0; h < 2; h++) {
                            float cv = acc[mt][nt][h * 2 + p];
                            if (tg[mt][h] == clsG) {
                                sP += fexp(32.0f * (0.1f - cv));
                            } else {
                                float nv = (cv < outl) ? ie : 1.0f;
                                sV += nv;
                                sN += fexp(32.0f * (cv + 0.1f) * nv);
                            }
                        }
                    }
#pragma unroll
                    for (int o = 4; o <= 16; o <<= 1) {
                        sP += __shfl_xor_sync(0xffffffffu, sP, o);
                        sN += __shfl_xor_sync(0xffffffffu, sN, o);
                        sV += __shfl_xor_sync(0xffffffffu, sV, o);
                    }
                    if ((lane >> 2) == 0) {
                        atomicAdd(&g_Spos[clsG], sP);
                        atomicAdd(&g_Sneg[clsG], sN);
                        atomicAdd(&g_Nsum[clsG], sV);
                    }
                }
            }
            // reset accumulators for next tile
#pragma unroll
            for (int i = 0; i < 4; i++)
#pragma unroll
                for (int j = 0; j < 4; j++)
#pragma unroll
                    for (int e = 0; e < 4; e++) acc[i][j][e] = 0.0f;
        }
    }
}

// ---------------- finalize (single block: race-free shared histogram) ----------------
#define FIN_SMEM (C_SZ * 4)
__global__ void __launch_bounds__(1024) finalizeKernel(const int* __restrict__ targets,
                                                       float* __restrict__ out) {
    extern __shared__ int scnt[];
    __shared__ float smr[4][1024];
    int tid = threadIdx.x;
    for (int c = tid; c < C_SZ; c += 1024) scnt[c] = 0;
    __syncthreads();
    atomicAdd(&scnt[targets[tid]], 1);   // blockDim == B_SZ == 1024
    __syncthreads();

    float posT = 0.0f, negT = 0.0f, posW = 0.0f, negW = 0.0f;
    for (int c = tid; c < C_SZ; c += 1024) {
        int cnt = scnt[c];
        if (cnt > 0) { posW += 1.0f; posT += log1pf(g_Spos[c]); }
        negT += log1pf(g_Sneg[c]);
        int Ncnt = B_SZ - cnt;
        float nm = g_Nsum[c] / fmaxf((float)Ncnt, 1.0f);
        if (Ncnt > 0) negW += nm;
    }
    smr[0][tid] = posT; smr[1][tid] = negT; smr[2][tid] = posW; smr[3][tid] = negW;
    __syncthreads();
    for (int s = 512; s > 0; s >>= 1) {
        if (tid < s) {
#pragma unroll
            for (int j = 0; j < 4; j++) smr[j][tid] += smr[j][tid + s];
        }
        __syncthreads();
    }
    if (tid == 0) out[0] = smr[0][0] / smr[2][0] + smr[1][0] / smr[3][0];
}

// ---------------- launch ----------------
extern "C" void kernel_launch(void* const* d_in, const int* in_sizes, int n_in,
                              void* d_out, int out_size) {
    const float* inputs  = (const float*)d_in[0];   // [B,E] f32
    const int*   targets = (const int*)d_in[1];     // [B]   i32
    const float* proxies = (const float*)d_in[2];   // [C,E] f32
    const float* effN    = (const float*)d_in[3];   // [C]
    const float* ls      = (const float*)d_in[4];   // [C]
    float* out = (float*)d_out;

    cudaFuncSetAttribute(mainHMMA, cudaFuncAttributeMaxDynamicSharedMemorySize, SM_BYTES);
    cudaFuncSetAttribute(finalizeKernel, cudaFuncAttributeMaxDynamicSharedMemorySize, FIN_SMEM);

    prepKernel<<<2624, 256>>>(inputs, proxies, effN, ls);
    mainHMMA<<<GRID_MAIN, 256, SM_BYTES>>>(targets);
    finalizeKernel<<<1, 1024, FIN_SMEM>>>(targets, out);
}